// round 1
// baseline (speedup 1.0000x reference)
#include <cuda_runtime.h>

#define N_ROI 1024
#define C_CH  256
#define FLAT  12544
#define HID   1024
#define EMB   256

// ---------------- scratch (no allocation allowed) ----------------
__device__ float g_wT[2304 * 256];                 // transposed conv weights [t][oc]
__device__ float g_x[(size_t)N_ROI * FLAT];        // conv output, flattened [n][c*49+o]
__device__ float g_h[(size_t)N_ROI * HID];         // fc1 output
__device__ float g_e[(size_t)N_ROI * EMB];         // normalized embeddings (row-major)
__device__ float g_eT[(size_t)EMB * N_ROI];        // transposed embeddings

// ---------------- weight transpose: conv_w[oc][ic][ky][kx] -> wT[ic*9+ky*3+kx][oc]
__global__ void wtrans_kernel(const float* __restrict__ w) {
    int idx = blockIdx.x * 256 + threadIdx.x;      // 2304*256 total
    int oc = idx / 2304;
    int t  = idx % 2304;
    g_wT[t * 256 + oc] = w[idx];
}

// ---------------- conv 3x3 stride2 pad1 + bias + relu ----------------
// block = one roi (n); thread = one output channel; 49 accumulators in regs.
#define ICB 16
__global__ __launch_bounds__(256) void conv_kernel(const float* __restrict__ feat,
                                                   const float* __restrict__ bias) {
    __shared__ float sin[ICB * 14 * 16];           // 14336 B, rows padded to 16 floats
    int n  = blockIdx.x;
    int oc = threadIdx.x;

    float acc[49];
#pragma unroll
    for (int o = 0; o < 49; o++) acc[o] = 0.f;

    const float* fbase = feat + (size_t)n * C_CH * 196;

    for (int ic0 = 0; ic0 < C_CH; ic0 += ICB) {
        __syncthreads();
        for (int idx = threadIdx.x; idx < ICB * 196; idx += 256) {
            int c  = idx / 196;
            int r  = idx % 196;
            int iy = r / 14, ix = r % 14;
            sin[(c * 14 + iy) * 16 + ix] = fbase[(ic0 + c) * 196 + r];
        }
        __syncthreads();

        for (int c = 0; c < ICB; c++) {
            int ic = ic0 + c;
            float w[9];
#pragma unroll
            for (int j = 0; j < 9; j++)
                w[j] = g_wT[(ic * 9 + j) * 256 + oc];

            const float* srow0 = &sin[c * 14 * 16];
#pragma unroll
            for (int iy = 0; iy < 14; iy++) {
                float r[16];
#pragma unroll
                for (int q = 0; q < 4; q++)
                    *(float4*)&r[q * 4] = *(const float4*)&srow0[iy * 16 + q * 4];
#pragma unroll
                for (int ky = 0; ky < 3; ky++) {
                    int oy2 = iy + 1 - ky;          // = 2*oy   (compile-time after unroll)
                    if (oy2 < 0 || oy2 > 12 || (oy2 & 1)) continue;
                    int oy = oy2 >> 1;
#pragma unroll
                    for (int kx = 0; kx < 3; kx++) {
                        float wv = w[ky * 3 + kx];
#pragma unroll
                        for (int ox = 0; ox < 7; ox++) {
                            int ix = 2 * ox + kx - 1;
                            if (ix >= 0 && ix < 14)
                                acc[oy * 7 + ox] += wv * r[ix];
                        }
                    }
                }
            }
        }
    }

    float b = bias[oc];
    // stage through smem for coalesced writes: 4 phases of 64 oc each
    __syncthreads();
    for (int p = 0; p < 4; p++) {
        if ((oc >> 6) == p) {
#pragma unroll
            for (int o = 0; o < 49; o++)
                sin[(oc & 63) * 49 + o] = fmaxf(acc[o] + b, 0.f);
        }
        __syncthreads();
        float4* dst = (float4*)(g_x + (size_t)n * FLAT + p * 3136);
        const float4* src = (const float4*)sin;
        for (int idx = threadIdx.x; idx < 784; idx += 256)
            dst[idx] = src[idx];
        __syncthreads();
    }
}

// ---------------- fc1: h = relu(x @ w1 + b1), 64x64x16 tiles ----------------
#define BM 64
#define BN 64
#define BK 16
__global__ __launch_bounds__(256) void fc1_kernel(const float* __restrict__ w1,
                                                  const float* __restrict__ b1) {
    __shared__ float As[BK][BM + 4];   // stride 68 floats (272B, 16B-aligned rows)
    __shared__ float Bs[BK][BN];

    int bn = blockIdx.x * BN;
    int bm = blockIdx.y * BM;
    int tid = threadIdx.x;
    int ty = tid >> 4, tx = tid & 15;

    int la_m = tid >> 2;
    int la_k = (tid & 3) * 4;
    int lb_k = tid >> 4;
    int lb_n = (tid & 15) * 4;

    const float* xa = g_x + (size_t)(bm + la_m) * FLAT + la_k;

    float acc[4][4];
#pragma unroll
    for (int i = 0; i < 4; i++)
#pragma unroll
        for (int j = 0; j < 4; j++) acc[i][j] = 0.f;

    for (int k0 = 0; k0 < FLAT; k0 += BK) {
        float4 av = *(const float4*)(xa + k0);
        float4 bv = *(const float4*)(w1 + (size_t)(k0 + lb_k) * HID + bn + lb_n);
        __syncthreads();
        As[la_k + 0][la_m] = av.x;
        As[la_k + 1][la_m] = av.y;
        As[la_k + 2][la_m] = av.z;
        As[la_k + 3][la_m] = av.w;
        *(float4*)&Bs[lb_k][lb_n] = bv;
        __syncthreads();
#pragma unroll
        for (int kk = 0; kk < BK; kk++) {
            float4 a = *(const float4*)&As[kk][ty * 4];
            float4 b = *(const float4*)&Bs[kk][tx * 4];
            float ar[4] = {a.x, a.y, a.z, a.w};
            float br[4] = {b.x, b.y, b.z, b.w};
#pragma unroll
            for (int i = 0; i < 4; i++)
#pragma unroll
                for (int j = 0; j < 4; j++)
                    acc[i][j] += ar[i] * br[j];
        }
    }

#pragma unroll
    for (int i = 0; i < 4; i++) {
        int row = bm + ty * 4 + i;
#pragma unroll
        for (int j = 0; j < 4; j++) {
            int col = bn + tx * 4 + j;
            g_h[(size_t)row * HID + col] = fmaxf(acc[i][j] + b1[col], 0.f);
        }
    }
}

// ---------------- fc2 + bias + L2-normalize; writes e and eT ----------------
__global__ __launch_bounds__(256) void fc2_kernel(const float* __restrict__ w2,
                                                  const float* __restrict__ b2) {
    __shared__ float hs[4][1024];
    __shared__ float red[256];
    int n0 = blockIdx.x * 4;
    int c  = threadIdx.x;

    for (int idx = c; idx < 4096; idx += 256) {
        int r = idx >> 10, k = idx & 1023;
        hs[r][k] = g_h[(size_t)(n0 + r) * HID + k];
    }
    __syncthreads();

    float bb = b2[c];
    float a0 = bb, a1 = bb, a2 = bb, a3 = bb;
#pragma unroll 4
    for (int k = 0; k < 1024; k++) {
        float w = w2[(size_t)k * 256 + c];
        a0 += hs[0][k] * w;
        a1 += hs[1][k] * w;
        a2 += hs[2][k] * w;
        a3 += hs[3][k] * w;
    }
    float acc[4] = {a0, a1, a2, a3};

    for (int r = 0; r < 4; r++) {
        red[c] = acc[r] * acc[r];
        __syncthreads();
        for (int s = 128; s > 0; s >>= 1) {
            if (c < s) red[c] += red[c + s];
            __syncthreads();
        }
        float v = acc[r] / sqrtf(red[0]);
        __syncthreads();
        g_e[(size_t)(n0 + r) * EMB + c] = v;
        g_eT[(size_t)c * N_ROI + (n0 + r)] = v;
    }
}

// ---------------- pairwise: logits[p] = sum_k |e_i[k]-e_j[k]|*wm[k] + bm ----------------
#define TI 16
__global__ __launch_bounds__(256) void pair_kernel(const float* __restrict__ wm,
                                                   const float* __restrict__ bm,
                                                   float* __restrict__ out) {
    int i0 = blockIdx.y * TI;
    int j0 = blockIdx.x * 256;
    if (j0 + 255 <= i0) return;                    // no valid (i<j) pair in this tile

    __shared__ float ei[TI][256];
    __shared__ float wms[256];
    int tid = threadIdx.x;
    wms[tid] = wm[tid];
#pragma unroll
    for (int r = 0; r < TI; r++)
        ei[r][tid] = g_e[(size_t)(i0 + r) * EMB + tid];
    __syncthreads();

    int j = j0 + tid;
    float acc[TI];
#pragma unroll
    for (int r = 0; r < TI; r++) acc[r] = 0.f;

#pragma unroll 4
    for (int k = 0; k < 256; k++) {
        float vj = g_eT[(size_t)k * N_ROI + j];
        float wk = wms[k];
#pragma unroll
        for (int r = 0; r < TI; r++)
            acc[r] += fabsf(ei[r][k] - vj) * wk;
    }

    float bmv = *bm;
#pragma unroll
    for (int r = 0; r < TI; r++) {
        int i = i0 + r;
        if (j > i) {
            int p = i * (2 * N_ROI - i - 1) / 2 + (j - i - 1);
            out[p] = acc[r] + bmv;
        }
    }
}

// ---------------- launch ----------------
extern "C" void kernel_launch(void* const* d_in, const int* in_sizes, int n_in,
                              void* d_out, int out_size) {
    const float* feat   = (const float*)d_in[0];
    // d_in[1] = ids (int64) — unused by the reference
    const float* conv_w = (const float*)d_in[2];
    const float* conv_b = (const float*)d_in[3];
    const float* w1     = (const float*)d_in[4];
    const float* b1     = (const float*)d_in[5];
    const float* w2     = (const float*)d_in[6];
    const float* b2     = (const float*)d_in[7];
    const float* wm     = (const float*)d_in[8];
    const float* bm     = (const float*)d_in[9];
    float* out = (float*)d_out;

    wtrans_kernel<<<2304, 256>>>(conv_w);
    conv_kernel<<<N_ROI, 256>>>(feat, conv_b);
    fc1_kernel<<<dim3(HID / BN, N_ROI / BM), 256>>>(w1, b1);
    fc2_kernel<<<N_ROI / 4, 256>>>(w2, b2);
    pair_kernel<<<dim3(N_ROI / 256, N_ROI / TI), 256>>>(wm, bm, out);
}